// round 10
// baseline (speedup 1.0000x reference)
#include <cuda_runtime.h>
#include <stdint.h>

// Problem shape (fixed by the dataset)
#define BATCH    8192
#define IN_DIM   4096
#define N_RULES  2048
#define KWORDS   128            // u32 bit-words along k
#define NGROUPS  64             // rule groups of 32 rules
#define GSPLIT   8              // k-splits per group (pack item granularity)
#define NPACK    (NGROUPS * GSPLIT)      // 512
#define NX       1024           // x items, 8 rows each
#define NOUT     1024           // out tiles: 64 groups x 16 row-slices
#define NITEMS   (NPACK + NOUT + NX + 1) // 2561 (+1 reset item)
#define GRID     444            // 148 SMs x 3 CTAs -> all resident (wave 1)
#define WAVE_IT  192            // per wave: 64 pack items + 128 out tiles

// Scratch (device globals — no allocation allowed)
__device__ uint32_t g_wbits[N_RULES * KWORDS];   // [r][w]
__device__ uint32_t g_abits[BATCH   * KWORDS];   // [b][w]
__device__ uint32_t g_wany8[GSPLIT  * N_RULES];  // per-split OR of rule words
__device__ uint32_t g_aflag[BATCH];              // 1 <=> row b has exact x==1.0f
__device__ uint32_t g_rsum [NPACK];              // per-pack-item OR (uncond. write)
// sync state: reset to 0 by the final item every call -> replay-deterministic
__device__ unsigned g_done[NGROUPS];             // splits completed per group
__device__ unsigned g_packdone, g_xdone, g_outdone;

__device__ __forceinline__ void spin_ge(volatile unsigned* p, unsigned tgt) {
    while (*p < tgt) __nanosleep(64);
}

// Rare general path: any weight-selected k with x[b,k] != 1 makes res > 0.
__device__ __forceinline__ float conj_general(int b, int r) {
    const uint32_t* A  = g_abits + b * KWORDS;
    const uint32_t* Wp = g_wbits + r * KWORDS;
    for (int i = 0; i < KWORDS; i++) {
        if (__ldcg(A + i) & __ldcg(Wp + i)) return 0.0f;
    }
    return 1.0f;
}

// ---------------------------------------------------------------------------
// Persistent fused kernel. Item id space (all spins point to SMALLER ids):
//   waves w=0..7: [w*192, +64) pack items (8 groups x 8 splits)
//                 [w*192+64, +128) out tiles (8 groups x 16 slices)
//   [1536, 2560): x items (spin: all pack done, then early-exit check)
//   2560: reset item (spin: all x + out done, then zero the counters)
// ---------------------------------------------------------------------------
__global__ void __launch_bounds__(256, 3)
fused_kernel(const float* __restrict__ W, const float* __restrict__ x,
             float* __restrict__ out) {
    __shared__ uint32_t sm_red[8][32];
    __shared__ __align__(16) float s_val[32];
    __shared__ uint32_t s_w[32];
    __shared__ uint32_t s_flag;
    int tid = threadIdx.x, wi = tid >> 5, lane = tid & 31;

    for (int p = blockIdx.x; p < NITEMS; p += GRID) {
        __syncthreads();                       // smem reuse guard between items
        if (p < NPACK + NOUT) {
            int wave = p / WAVE_IT;
            int q    = p - wave * WAVE_IT;
            if (q < 64) {
                // ---------------- pack item: 32 rules x 512 k ----------------
                int group = wave * 8 + (q & 7);
                int split = q >> 3;
                int r = group * 32 + lane;     // lanes across rules: coalesced
                uint32_t acc = 0;
#pragma unroll
                for (int t = 0; t < 2; t++) {
                    int w = split * 16 + t * 8 + wi;
                    const float* ptr = W + (size_t)(w * 32) * N_RULES + r;
                    uint32_t word = 0;
#pragma unroll
                    for (int j = 0; j < 32; j++) {
                        if (ptr[(size_t)j * N_RULES] > 0.5f) word |= (1u << j);
                    }
                    g_wbits[r * KWORDS + w] = word;
                    acc |= word;
                }
                sm_red[wi][lane] = acc;
                __syncthreads();
                if (wi == 0) {
                    uint32_t o = 0;
#pragma unroll
                    for (int k2 = 0; k2 < 8; k2++) o |= sm_red[k2][lane];
                    g_wany8[split * N_RULES + r] = o;
                    uint32_t any = __reduce_or_sync(0xFFFFFFFFu, o);
                    if (lane == 0) g_rsum[wave * 64 + q] = any;
                }
                __threadfence();               // all threads: stores -> visible
                __syncthreads();
                if (tid == 0) {
                    atomicAdd(&g_done[group], 1u);     // release group split
                    atomicAdd(&g_packdone, 1u);
                }
            } else {
                // ---------------- out tile: 32 rules x 512 rows --------------
                int q2    = q - 64;
                int rg    = wave * 8 + (q2 & 7);
                int slice = q2 >> 3;
                if (tid == 0) { spin_ge(&g_done[rg], GSPLIT); __threadfence(); }
                __syncthreads();
                if (tid < 32) {
                    int r = rg * 32 + tid;
                    uint32_t o = 0;
#pragma unroll
                    for (int s2 = 0; s2 < GSPLIT; s2++)
                        o |= __ldcg(g_wany8 + s2 * N_RULES + r);
                    s_w[tid]   = o;
                    s_val[tid] = (o == 0u) ? 1.0f : 0.0f;
                    uint32_t any = __reduce_or_sync(0xFFFFFFFFu, o);
                    if (tid == 0) s_flag = (any == 0u) ? 1u : 0u;
                }
                __syncthreads();
                bool empty = (s_flag != 0u);
                if (!empty) {                  // rare: need aflag -> wait for x
                    if (tid == 0) { spin_ge(&g_xdone, NX); __threadfence(); }
                    __syncthreads();
                }
                int chunk  = tid & 7;          // float4 chunk within 32 rules
                int rowoff = tid >> 3;         // 0..31
                float4 v0 = *reinterpret_cast<const float4*>(s_val + chunk * 4);
                float4* o4 = reinterpret_cast<float4*>(out);
                int b0 = slice * 512;
#pragma unroll
                for (int it = 0; it < 16; it++) {
                    int b = b0 + it * 32 + rowoff;
                    float4 o;
                    if (empty || !__ldcg(g_aflag + b)) {
                        o = v0;                // dominant path
                    } else {
                        int r0 = rg * 32 + chunk * 4;
                        o.x = (s_w[chunk*4+0] == 0u) ? 1.0f : conj_general(b, r0+0);
                        o.y = (s_w[chunk*4+1] == 0u) ? 1.0f : conj_general(b, r0+1);
                        o.z = (s_w[chunk*4+2] == 0u) ? 1.0f : conj_general(b, r0+2);
                        o.w = (s_w[chunk*4+3] == 0u) ? 1.0f : conj_general(b, r0+3);
                    }
                    o4[(size_t)b * 512 + rg * 8 + chunk] = o;
                }
                __threadfence();
                __syncthreads();
                if (tid == 0) atomicAdd(&g_outdone, 1u);
            }
        } else if (p < NPACK + NOUT + NX) {
            // ------------------- x item: 8 rows, early-exit -------------------
            int i = p - (NPACK + NOUT);
            if (tid == 0) { spin_ge(&g_packdone, NPACK); __threadfence(); }
            __syncthreads();
            uint2 rs = __ldcg(reinterpret_cast<const uint2*>(g_rsum) + tid);
            if (__syncthreads_or((rs.x | rs.y) != 0u)) {
                for (int rr = 0; rr < 8; rr++) {
                    int b = i * 8 + rr;
                    const float* px = x + (size_t)b * IN_DIM + wi * 512;
                    uint32_t wrd[16];
                    uint32_t ones = 0xFFFFFFFFu;
#pragma unroll
                    for (int u = 0; u < 16; u++) {
                        float v = px[u * 32 + lane];     // coalesced 128B line
                        wrd[u] = __ballot_sync(0xFFFFFFFFu, v != 1.0f);
                        ones &= wrd[u];
                    }
                    if (lane == 0) {
                        uint4* qq = reinterpret_cast<uint4*>(g_abits + b * KWORDS + wi * 16);
                        qq[0] = make_uint4(wrd[0],  wrd[1],  wrd[2],  wrd[3]);
                        qq[1] = make_uint4(wrd[4],  wrd[5],  wrd[6],  wrd[7]);
                        qq[2] = make_uint4(wrd[8],  wrd[9],  wrd[10], wrd[11]);
                        qq[3] = make_uint4(wrd[12], wrd[13], wrd[14], wrd[15]);
                        sm_red[0][wi] = (ones == 0xFFFFFFFFu) ? 1u : 0u;
                    }
                    __syncthreads();
                    if (tid == 0) {
                        uint32_t a = sm_red[0][0] & sm_red[0][1] & sm_red[0][2] &
                                     sm_red[0][3] & sm_red[0][4] & sm_red[0][5] &
                                     sm_red[0][6] & sm_red[0][7];
                        g_aflag[b] = a ? 0u : 1u;
                    }
                    __syncthreads();
                }
            }
            __threadfence();
            __syncthreads();
            if (tid == 0) atomicAdd(&g_xdone, 1u);     // ALWAYS signal
        } else {
            // ------------------- reset item (id 2560, runs last) --------------
            if (tid == 0) {
                spin_ge(&g_xdone, NX);
                spin_ge(&g_outdone, NOUT);
                for (int g2 = 0; g2 < NGROUPS; g2++)
                    ((volatile unsigned*)g_done)[g2] = 0u;
                *(volatile unsigned*)&g_packdone = 0u;
                *(volatile unsigned*)&g_xdone    = 0u;
                *(volatile unsigned*)&g_outdone  = 0u;
                __threadfence();
            }
        }
    }
}

// ---------------------------------------------------------------------------
extern "C" void kernel_launch(void* const* d_in, const int* in_sizes, int n_in,
                              void* d_out, int out_size) {
    const float* x = (const float*)d_in[0];   // [BATCH, IN_DIM]
    const float* W = (const float*)d_in[1];   // [IN_DIM, N_RULES]
    float* out = (float*)d_out;               // [BATCH, N_RULES]

    (void)in_sizes; (void)n_in; (void)out_size;

    fused_kernel<<<GRID, 256>>>(W, x, out);   // single persistent launch
}

// round 11
// speedup vs baseline: 1.5165x; 1.5165x over previous
#include <cuda_runtime.h>
#include <stdint.h>

// Problem shape (fixed by the dataset)
#define BATCH   8192
#define IN_DIM  4096
#define N_RULES 2048
#define KWORDS  128              // u32 bit-words along k
#define PBLOCKS 1024             // pack_w tiles: 8 rule-groups x 128 w-layers
#define XROWS   8                // rows per pack_x block

// Scratch (device globals — no allocation allowed)
__device__ uint32_t g_wbitsT[KWORDS * N_RULES];  // TRANSPOSED: [w][r]
__device__ uint32_t g_abits [BATCH  * KWORDS];   // [b][w]
__device__ uint32_t g_aflag [BATCH];             // 1 <=> row b has exact x==1.0f
__device__ uint32_t g_rsum  [PBLOCKS];           // per-tile OR (uncond. write)

// ---------------------------------------------------------------------------
// Kernel 1: pack W > 0.5, tile-transpose form. Block owns a 32k x 256rule
// tile = 32KB of CONTIGUOUS W. Phase 1: 8 independent coalesced float4 loads
// per thread (no dependency chain on the load stream). Compare -> pack 4
// bool-bytes into a u32 -> conflict-free smem store. Phase 2: thread owns one
// rule, assembles its 32-bit word from 32 smem bytes, stores coalesced to the
// transposed layout. Unconditional per-tile rsum (no atomics, no init).
// ---------------------------------------------------------------------------
__global__ __launch_bounds__(256) void pack_w_kernel(const float* __restrict__ W) {
    __shared__ uint32_t sm[32 * 64];     // [row j][c4] : 4 bool-bytes per u32
    int tid = threadIdx.x;
    int rg  = blockIdx.x & 7;            // rule-group (256 rules)
    int w   = blockIdx.x >> 3;           // w-layer (32 k-rows)

    const float4* W4 = reinterpret_cast<const float4*>(W);
    size_t base = (size_t)(w * 32) * (N_RULES / 4) + rg * 64;
#pragma unroll
    for (int u = 0; u < 8; u++) {
        int fi  = u * 256 + tid;         // [0, 2048)
        int row = fi >> 6;               // k-row within tile
        int c4  = fi & 63;               // float4 column
        float4 v = W4[base + (size_t)row * (N_RULES / 4) + c4];
        uint32_t b = (v.x > 0.5f ? 0x01u : 0u) |
                     (v.y > 0.5f ? 0x0100u : 0u) |
                     (v.z > 0.5f ? 0x010000u : 0u) |
                     (v.w > 0.5f ? 0x01000000u : 0u);
        sm[row * 64 + c4] = b;           // conflict-free (consecutive u32)
    }
    __syncthreads();

    // Phase 2: thread owns rule (rg*256 + tid); gather its 32 bool-bytes.
    const uint8_t* sm8 = reinterpret_cast<const uint8_t*>(sm);
    uint32_t word = 0;
#pragma unroll
    for (int j = 0; j < 32; j++) {
        word |= (uint32_t)(sm8[j * 256 + tid] & 1u) << j;
    }
    g_wbitsT[(size_t)w * N_RULES + rg * 256 + tid] = word;  // coalesced 1KB

    uint32_t any = __syncthreads_or(word != 0u) ? 1u : 0u;
    if (tid == 0) g_rsum[blockIdx.x] = any;   // always written each replay
}

// ---------------------------------------------------------------------------
// Kernel 2: pack x, XROWS rows per block. EARLY EXIT: if every rule is empty
// (all g_rsum == 0), abits/aflag can never be consumed -> skip the 128MB read.
// ---------------------------------------------------------------------------
__global__ __launch_bounds__(256) void pack_x_kernel(const float* __restrict__ x) {
    uint4 rs = reinterpret_cast<const uint4*>(g_rsum)[threadIdx.x]; // 256*4=1024
    if (!__syncthreads_or((rs.x | rs.y | rs.z | rs.w) != 0u)) return;

    __shared__ uint32_t sm_ok[8];
    int wi   = threadIdx.x >> 5;
    int lane = threadIdx.x & 31;

    for (int i = 0; i < XROWS; i++) {
        int b = blockIdx.x * XROWS + i;
        const float* px = x + (size_t)b * IN_DIM + wi * 512;
        uint32_t wrd[16];
        uint32_t ones = 0xFFFFFFFFu;
#pragma unroll
        for (int u = 0; u < 16; u++) {
            float v = px[u * 32 + lane];                // coalesced 128B line
            wrd[u] = __ballot_sync(0xFFFFFFFFu, v != 1.0f);
            ones &= wrd[u];
        }
        if (lane == 0) {
            uint4* q = reinterpret_cast<uint4*>(g_abits + b * KWORDS + wi * 16);
            q[0] = make_uint4(wrd[0],  wrd[1],  wrd[2],  wrd[3]);
            q[1] = make_uint4(wrd[4],  wrd[5],  wrd[6],  wrd[7]);
            q[2] = make_uint4(wrd[8],  wrd[9],  wrd[10], wrd[11]);
            q[3] = make_uint4(wrd[12], wrd[13], wrd[14], wrd[15]);
            sm_ok[wi] = (ones == 0xFFFFFFFFu) ? 1u : 0u;
        }
        __syncthreads();
        if (threadIdx.x == 0) {
            uint32_t a = sm_ok[0] & sm_ok[1] & sm_ok[2] & sm_ok[3] &
                         sm_ok[4] & sm_ok[5] & sm_ok[6] & sm_ok[7];
            g_aflag[b] = a ? 0u : 1u;                   // 1 <=> row has exact 1.0
        }
        __syncthreads();
    }
}

// Rare general path: any weight-selected k with x[b,k] != 1 makes res > 0.
// (wbits transposed; strided reads fine on this cold path.)
__device__ __forceinline__ float conj_general(int b, int r) {
    const uint32_t* A = g_abits + b * KWORDS;
    for (int i = 0; i < KWORDS; i++) {
        if (A[i] & g_wbitsT[(size_t)i * N_RULES + r]) return 0.0f;
    }
    return 1.0f;
}

// ---------------------------------------------------------------------------
// Kernel 3: output. Block owns 32 rules x 512 rows. Fold wany for its 32
// rules directly from wbitsT (16KB, L2-hit, coalesced 128B per w-row), then
// stream coalesced float4 writes. Grid 64 x 16 = 1024 blocks.
// ---------------------------------------------------------------------------
__global__ __launch_bounds__(256) void out_kernel(float* __restrict__ out) {
    __shared__ uint32_t sm_red[8][32];
    __shared__ __align__(16) float s_val[32];   // aflag==0 answer per rule
    __shared__ uint32_t s_w[32];                // folded wany per rule
    __shared__ uint32_t s_empty;
    int tid = threadIdx.x;
    int rg  = blockIdx.x & 63;                  // rule-group: 32 rules
    int b0  = (blockIdx.x >> 6) * 512;          // row-slice base

    {   // fold wany over 128 w-layers: thread = (w-chunk of 16) x (1 rule)
        int r  = rg * 32 + (tid & 31);
        int wc = tid >> 5;                      // 0..7
        uint32_t o = 0;
#pragma unroll
        for (int i = 0; i < 16; i++)
            o |= g_wbitsT[(size_t)(wc * 16 + i) * N_RULES + r];
        sm_red[wc][tid & 31] = o;
    }
    __syncthreads();
    if (tid < 32) {
        uint32_t o = sm_red[0][tid] | sm_red[1][tid] | sm_red[2][tid] |
                     sm_red[3][tid] | sm_red[4][tid] | sm_red[5][tid] |
                     sm_red[6][tid] | sm_red[7][tid];
        s_w[tid]   = o;
        s_val[tid] = (o == 0u) ? 1.0f : 0.0f;
        uint32_t any = __reduce_or_sync(0xFFFFFFFFu, o);
        if (tid == 0) s_empty = (any == 0u) ? 1u : 0u;
    }
    __syncthreads();

    bool empty  = (s_empty != 0u);
    int  chunk  = tid & 7;                      // float4 chunk within 32 rules
    int  rowoff = tid >> 3;                     // 0..31
    float4 v0 = *reinterpret_cast<const float4*>(s_val + chunk * 4);
    float4* o4 = reinterpret_cast<float4*>(out);

#pragma unroll
    for (int it = 0; it < 16; it++) {
        int b = b0 + it * 32 + rowoff;
        float4 o;
        if (empty || !g_aflag[b]) {
            o = v0;                             // dominant path
        } else {
            int r0 = rg * 32 + chunk * 4;
            o.x = (s_w[chunk*4+0] == 0u) ? 1.0f : conj_general(b, r0 + 0);
            o.y = (s_w[chunk*4+1] == 0u) ? 1.0f : conj_general(b, r0 + 1);
            o.z = (s_w[chunk*4+2] == 0u) ? 1.0f : conj_general(b, r0 + 2);
            o.w = (s_w[chunk*4+3] == 0u) ? 1.0f : conj_general(b, r0 + 3);
        }
        o4[(size_t)b * 512 + rg * 8 + chunk] = o;
    }
}

// ---------------------------------------------------------------------------
extern "C" void kernel_launch(void* const* d_in, const int* in_sizes, int n_in,
                              void* d_out, int out_size) {
    const float* x = (const float*)d_in[0];   // [BATCH, IN_DIM]
    const float* W = (const float*)d_in[1];   // [IN_DIM, N_RULES]
    float* out = (float*)d_out;               // [BATCH, N_RULES]

    (void)in_sizes; (void)n_in; (void)out_size;

    pack_w_kernel<<<PBLOCKS, 256>>>(W);            // 1024 tiles, pure streaming
    pack_x_kernel<<<BATCH / XROWS, 256>>>(x);      // 1024 blocks (early exit)
    out_kernel<<<64 * 16, 256>>>(out);             // 1024 blocks
}